// round 9
// baseline (speedup 1.0000x reference)
#include <cuda_runtime.h>

// Unfold (im2col) for x:(B=16, C=128, H=64, W=64), k=3, pad=1.
// out[b, c*9 + p, h*W + w] = x[b, c, h+dh-1, w+dw-1] (zero-padded), p = dh*3+dw.
// DRAM-write bound: 302 MB compulsory write; measured write ceiling ~5.5 TB/s.
//
// R8: h-quad per thread. 6 aligned LDG.128 (rows h-1..h+4) serve the 12
// row-outputs of rows h..h+3 (36 STG.128, maximally deep store burst).
// Edge halo values via warp shuffle (wg == lane&15: shuffles stay in-row
// except at the zero-pad lanes, which the predicates mask).
// Invariant preserved: every STG warp-instruction covers 512B contiguous.

#define B_ 16
#define C_ 128
#define H_ 64
#define W_ 64
#define PLANE (H_ * W_)   // 4096

__global__ __launch_bounds__(256) void unfold_kernel(
    const float* __restrict__ x, float* __restrict__ out)
{
    int idx = blockIdx.x * blockDim.x + threadIdx.x;
    // Each thread handles 4 consecutive w of FOUR rows: h = 4*hq .. 4*hq+3.
    // idx layout: [bc (11b)] [hq (4b)] [wg (4b)]
    int wg = idx & 15;           // w-group 0..15 (== lane & 15)
    int hq = (idx >> 4) & 15;    // h-quad 0..15
    int bc = idx >> 8;           // b*C + c, 0..2047
    int w0 = wg << 2;            // 0,4,...,60
    int h0 = hq << 2;            // 0,4,...,60

    const float* plane = x + (size_t)bc * PLANE;

    // Front-batch 6 aligned float4 loads: rows h0-1 .. h0+4.
    float4 a[6];
#pragma unroll
    for (int r = 0; r < 6; r++) {
        int hh = h0 + r - 1;
        if (hh >= 0 && hh < H_) {
            a[r] = *reinterpret_cast<const float4*>(plane + hh * W_ + w0);
        } else {
            a[r] = make_float4(0.f, 0.f, 0.f, 0.f);
        }
    }

    // Edge halo values from neighbor lanes (in-row; pad lanes masked).
    float e0[6], e5[6];
#pragma unroll
    for (int r = 0; r < 6; r++) {
        float left  = __shfl_up_sync(0xffffffffu, a[r].w, 1);
        float right = __shfl_down_sync(0xffffffffu, a[r].x, 1);
        e0[r] = (wg == 0)  ? 0.0f : left;
        e5[r] = (wg == 15) ? 0.0f : right;
    }

    // 36 fully coalesced STG.128: output rows h0+hr (hr=0..3) use a[hr..hr+2].
    float* outp = out + (size_t)bc * 9 * PLANE + h0 * W_ + w0;
#pragma unroll
    for (int hr = 0; hr < 4; hr++) {            // output row h0+hr
        float* obase = outp + hr * W_;
#pragma unroll
        for (int r = 0; r < 3; r++) {           // kernel row
            int s = hr + r;                     // source row index into a[]
            float* op = obase + (size_t)(r * 3) * PLANE;
            *reinterpret_cast<float4*>(op)             = make_float4(e0[s],  a[s].x, a[s].y, a[s].z);
            *reinterpret_cast<float4*>(op + PLANE)     = a[s];
            *reinterpret_cast<float4*>(op + 2 * PLANE) = make_float4(a[s].y, a[s].z, a[s].w, e5[s]);
        }
    }
}

extern "C" void kernel_launch(void* const* d_in, const int* in_sizes, int n_in,
                              void* d_out, int out_size)
{
    const float* x = (const float*)d_in[0];
    // d_in[1] is the identity "weights" buffer — unused (eye(9) by construction).
    float* out = (float*)d_out;

    const int total  = B_ * C_ * (H_ / 4) * (W_ / 4);  // 524,288 threads
    const int tpb    = 256;
    const int blocks = total / tpb;                    // 2048
    unfold_kernel<<<blocks, tpb>>>(x, out);
}

// round 10
// speedup vs baseline: 1.0560x; 1.0560x over previous
#include <cuda_runtime.h>
#include <cstdint>

// Unfold (im2col) for x:(B=16, C=128, H=64, W=64), k=3, pad=1.
// out[b, c*9 + p, h*W + w] = x[b, c, h+dh-1, w+dw-1] (zero-padded), p = dh*3+dw.
// DRAM-write bound: 302 MB compulsory write; measured ~5.5 TB/s across 6 shapes.
//
// R9: 256-bit vector memory ops (sm_100a+ PTX .v8.b32). 8 outputs/thread,
// 3x LDG.256 + 9x STG.256. Each STG warp-instruction covers 1024B contiguous
// (lane writes 32B, lanes consecutive) — halves instruction count and L1
// wavefront-queue entries per byte vs the float4 version.

#define B_ 16
#define C_ 128
#define H_ 64
#define W_ 64
#define PLANE (H_ * W_)   // 4096

__device__ __forceinline__ void ldg256(const float* p, float* f) {
    uint32_t r0, r1, r2, r3, r4, r5, r6, r7;
    asm volatile("ld.global.v8.b32 {%0,%1,%2,%3,%4,%5,%6,%7}, [%8];"
                 : "=r"(r0), "=r"(r1), "=r"(r2), "=r"(r3),
                   "=r"(r4), "=r"(r5), "=r"(r6), "=r"(r7)
                 : "l"(p));
    f[0] = __uint_as_float(r0); f[1] = __uint_as_float(r1);
    f[2] = __uint_as_float(r2); f[3] = __uint_as_float(r3);
    f[4] = __uint_as_float(r4); f[5] = __uint_as_float(r5);
    f[6] = __uint_as_float(r6); f[7] = __uint_as_float(r7);
}

__device__ __forceinline__ void stg256(float* p,
    float f0, float f1, float f2, float f3,
    float f4, float f5, float f6, float f7) {
    asm volatile("st.global.v8.b32 [%0], {%1,%2,%3,%4,%5,%6,%7,%8};"
                 :: "l"(p),
                    "r"(__float_as_uint(f0)), "r"(__float_as_uint(f1)),
                    "r"(__float_as_uint(f2)), "r"(__float_as_uint(f3)),
                    "r"(__float_as_uint(f4)), "r"(__float_as_uint(f5)),
                    "r"(__float_as_uint(f6)), "r"(__float_as_uint(f7))
                 : "memory");
}

__global__ __launch_bounds__(256) void unfold_kernel(
    const float* __restrict__ x, float* __restrict__ out)
{
    int idx = blockIdx.x * blockDim.x + threadIdx.x;
    // Each thread handles 8 consecutive w of one (b, c, h) row.
    // idx layout: [bc (11b)] [h (6b)] [wg (3b)]; wg == lane & 7.
    int wg = idx & 7;            // w-group 0..7
    int h  = (idx >> 3) & 63;    // 0..63
    int bc = idx >> 9;           // b*C + c, 0..2047
    int w0 = wg << 3;            // 0,8,...,56  (32B-aligned in floats)

    const float* plane = x + (size_t)bc * PLANE;

    // Front-batch 3 aligned 256-bit loads: rows h-1, h, h+1 (8 floats each).
    float f[3][8];
#pragma unroll
    for (int r = 0; r < 3; r++) {
        int hh = h + r - 1;
        if (hh >= 0 && hh < H_) {
            ldg256(plane + hh * W_ + w0, f[r]);
        } else {
#pragma unroll
            for (int c = 0; c < 8; c++) f[r][c] = 0.0f;
        }
    }

    // Edge halo values from neighbor lanes (in-row: wg == lane&7, so the
    // shuffle crosses an h boundary only at wg==0 / wg==7, the pad lanes).
    float e0[3], e5[3];
#pragma unroll
    for (int r = 0; r < 3; r++) {
        float left  = __shfl_up_sync(0xffffffffu, f[r][7], 1);
        float right = __shfl_down_sync(0xffffffffu, f[r][0], 1);
        e0[r] = (wg == 0) ? 0.0f : left;
        e5[r] = (wg == 7) ? 0.0f : right;
    }

    // 9 STG.256, each warp-instruction = 1024B contiguous.
    float* outp = out + (size_t)bc * 9 * PLANE + h * W_ + w0;
#pragma unroll
    for (int r = 0; r < 3; r++) {
        float* op = outp + (size_t)(r * 3) * PLANE;
        // dw = -1: window w0-1 .. w0+6
        stg256(op,
               e0[r],   f[r][0], f[r][1], f[r][2],
               f[r][3], f[r][4], f[r][5], f[r][6]);
        // dw = 0: window w0 .. w0+7
        stg256(op + PLANE,
               f[r][0], f[r][1], f[r][2], f[r][3],
               f[r][4], f[r][5], f[r][6], f[r][7]);
        // dw = +1: window w0+1 .. w0+8
        stg256(op + 2 * PLANE,
               f[r][1], f[r][2], f[r][3], f[r][4],
               f[r][5], f[r][6], f[r][7], e5[r]);
    }
}

extern "C" void kernel_launch(void* const* d_in, const int* in_sizes, int n_in,
                              void* d_out, int out_size)
{
    const float* x = (const float*)d_in[0];
    // d_in[1] is the identity "weights" buffer — unused (eye(9) by construction).
    float* out = (float*)d_out;

    const int total  = B_ * C_ * H_ * (W_ / 8);  // 1,048,576 threads
    const int tpb    = 256;
    const int blocks = total / tpb;              // 4096
    unfold_kernel<<<blocks, tpb>>>(x, out);
}

// round 11
// speedup vs baseline: 1.1101x; 1.0513x over previous
#include <cuda_runtime.h>
#include <cstdint>

// Unfold (im2col) for x:(B=16, C=128, H=64, W=64), k=3, pad=1.
// out[b, c*9 + p, h*W + w] = x[b, c, h+dh-1, w+dw-1] (zero-padded), p = dh*3+dw.
//
// R10 = R9 (8 outputs/thread, LDG.256 / STG.256, shuffle halo) + L2 policy:
//   loads : ld.global.nc.L2::evict_last  (pin 33.5MB input in 126MB L2;
//           3x h-reuse then hits L2 instead of re-fetching DRAM)
//   stores: st.global.L2::evict_first    (302MB write-once stream, fully
//           covered lines, never re-read — don't let it thrash the input)

#define B_ 16
#define C_ 128
#define H_ 64
#define W_ 64
#define PLANE (H_ * W_)   // 4096

__device__ __forceinline__ void ldg256_el(const float* p, float* f) {
    uint32_t r0, r1, r2, r3, r4, r5, r6, r7;
    asm volatile("ld.global.nc.L2::evict_last.v8.b32 {%0,%1,%2,%3,%4,%5,%6,%7}, [%8];"
                 : "=r"(r0), "=r"(r1), "=r"(r2), "=r"(r3),
                   "=r"(r4), "=r"(r5), "=r"(r6), "=r"(r7)
                 : "l"(p));
    f[0] = __uint_as_float(r0); f[1] = __uint_as_float(r1);
    f[2] = __uint_as_float(r2); f[3] = __uint_as_float(r3);
    f[4] = __uint_as_float(r4); f[5] = __uint_as_float(r5);
    f[6] = __uint_as_float(r6); f[7] = __uint_as_float(r7);
}

__device__ __forceinline__ void stg256_ef(float* p,
    float f0, float f1, float f2, float f3,
    float f4, float f5, float f6, float f7) {
    asm volatile("st.global.L2::evict_first.v8.b32 [%0], {%1,%2,%3,%4,%5,%6,%7,%8};"
                 :: "l"(p),
                    "r"(__float_as_uint(f0)), "r"(__float_as_uint(f1)),
                    "r"(__float_as_uint(f2)), "r"(__float_as_uint(f3)),
                    "r"(__float_as_uint(f4)), "r"(__float_as_uint(f5)),
                    "r"(__float_as_uint(f6)), "r"(__float_as_uint(f7))
                 : "memory");
}

__global__ __launch_bounds__(256) void unfold_kernel(
    const float* __restrict__ x, float* __restrict__ out)
{
    int idx = blockIdx.x * blockDim.x + threadIdx.x;
    // Each thread handles 8 consecutive w of one (b, c, h) row.
    // idx layout: [bc (11b)] [h (6b)] [wg (3b)]; wg == lane & 7.
    int wg = idx & 7;            // w-group 0..7
    int h  = (idx >> 3) & 63;    // 0..63
    int bc = idx >> 9;           // b*C + c, 0..2047
    int w0 = wg << 3;            // 0,8,...,56  (32B-aligned in floats)

    const float* plane = x + (size_t)bc * PLANE;

    // Front-batch 3 aligned 256-bit loads: rows h-1, h, h+1 (8 floats each).
    float f[3][8];
#pragma unroll
    for (int r = 0; r < 3; r++) {
        int hh = h + r - 1;
        if (hh >= 0 && hh < H_) {
            ldg256_el(plane + hh * W_ + w0, f[r]);
        } else {
#pragma unroll
            for (int c = 0; c < 8; c++) f[r][c] = 0.0f;
        }
    }

    // Edge halo values from neighbor lanes (in-row: wg == lane&7, so the
    // shuffle crosses an h boundary only at wg==0 / wg==7, the pad lanes).
    float e0[3], e5[3];
#pragma unroll
    for (int r = 0; r < 3; r++) {
        float left  = __shfl_up_sync(0xffffffffu, f[r][7], 1);
        float right = __shfl_down_sync(0xffffffffu, f[r][0], 1);
        e0[r] = (wg == 0) ? 0.0f : left;
        e5[r] = (wg == 7) ? 0.0f : right;
    }

    // 9 STG.256, each warp-instruction = 1024B contiguous, evict-first.
    float* outp = out + (size_t)bc * 9 * PLANE + h * W_ + w0;
#pragma unroll
    for (int r = 0; r < 3; r++) {
        float* op = outp + (size_t)(r * 3) * PLANE;
        // dw = -1: window w0-1 .. w0+6
        stg256_ef(op,
                  e0[r],   f[r][0], f[r][1], f[r][2],
                  f[r][3], f[r][4], f[r][5], f[r][6]);
        // dw = 0: window w0 .. w0+7
        stg256_ef(op + PLANE,
                  f[r][0], f[r][1], f[r][2], f[r][3],
                  f[r][4], f[r][5], f[r][6], f[r][7]);
        // dw = +1: window w0+1 .. w0+8
        stg256_ef(op + 2 * PLANE,
                  f[r][1], f[r][2], f[r][3], f[r][4],
                  f[r][5], f[r][6], f[r][7], e5[r]);
    }
}

extern "C" void kernel_launch(void* const* d_in, const int* in_sizes, int n_in,
                              void* d_out, int out_size)
{
    const float* x = (const float*)d_in[0];
    // d_in[1] is the identity "weights" buffer — unused (eye(9) by construction).
    float* out = (float*)d_out;

    const int total  = B_ * C_ * H_ * (W_ / 8);  // 1,048,576 threads
    const int tpb    = 256;
    const int blocks = total / tpb;              // 4096
    unfold_kernel<<<blocks, tpb>>>(x, out);
}